// round 1
// baseline (speedup 1.0000x reference)
#include <cuda_runtime.h>
#include <cstdint>

typedef unsigned long long ull;

// ---------------- problem constants ----------------
#define B_   4
#define F_   9
#define MP_  100
#define P_   12000
#define C_   64
#define NY_  400
#define NX_  400
#define NXO_ 4          // NX / POOL_W
#define NPTS (B_ * P_)  // 48000
#define NWIN (B_ * NY_ * NXO_)  // 6400
#define NOUT (B_ * C_ * NY_ * NXO_) // 409600

// main kernel tiling
#define TPB  256
#define NPB  32          // points per block (one per lane)
#define MPT  10          // mp per chunk
#define NCH  (MP_ / MPT) // 10 chunks
#define XSN  (F_ * MPT * NPB) // 2880 floats staged per chunk

// ---------------- device scratch (no allocs allowed) ----------------
__device__ ull   g_w1p[F_ * 32];   // packed pairs: [f][q] -> (w1'[2q][f], w1'[2q+1][f])
__device__ ull   g_b1p[32];
__device__ ull   g_w2p[32 * 64];   // [q][c] -> (w2'[2q][c], w2'[2q+1][c])
__device__ ull   g_b2p[32];
__device__ float g_z[C_];
__device__ int   g_cnt[NWIN];

// ---------------- f32x2 helpers (Blackwell packed fp32) ----------------
__device__ __forceinline__ ull ffma2(ull a, ull b, ull c) {
    ull d;
    asm("fma.rn.f32x2 %0, %1, %2, %3;" : "=l"(d) : "l"(a), "l"(b), "l"(c));
    return d;
}
__device__ __forceinline__ ull fpack(float x, float y) {
    ull r;
    asm("mov.b64 %0, {%1, %2};" : "=l"(r) : "f"(x), "f"(y));
    return r;
}
__device__ __forceinline__ ull fdup(float x) {
    ull r;
    asm("mov.b64 %0, {%1, %2};" : "=l"(r) : "f"(x), "f"(x));
    return r;
}
__device__ __forceinline__ void funpack(ull v, float& x, float& y) {
    asm("mov.b64 {%0, %1}, %2;" : "=f"(x), "=f"(y) : "l"(v));
}
__device__ __forceinline__ ull fmax2(ull a, ull b) {
    float ax, ay, bx, by;
    funpack(a, ax, ay);
    funpack(b, bx, by);
    return fpack(fmaxf(ax, bx), fmaxf(ay, by));
}

// ---------------- prep: fold BN into weights, pack pairs ----------------
__global__ void k_prep(const float* __restrict__ w1, const float* __restrict__ b1,
                       const float* __restrict__ g1, const float* __restrict__ be1,
                       const float* __restrict__ m1, const float* __restrict__ v1,
                       const float* __restrict__ w2, const float* __restrict__ b2,
                       const float* __restrict__ g2, const float* __restrict__ be2,
                       const float* __restrict__ m2, const float* __restrict__ v2) {
    __shared__ float s1[C_], bb1[C_], s2[C_], bb2[C_];
    int t = threadIdx.x;
    if (t < C_) {
        float s = g1[t] * rsqrtf(v1[t] + 1e-3f);
        s1[t] = s;
        bb1[t] = b1[t] * s + be1[t] - m1[t] * s;
        float ss = g2[t] * rsqrtf(v2[t] + 1e-3f);
        s2[t] = ss;
        float bz = b2[t] * ss + be2[t] - m2[t] * ss;
        bb2[t] = bz;
        g_z[t] = fmaxf(bz, 0.0f);
    }
    __syncthreads();
    for (int i = t; i < F_ * 32; i += blockDim.x) {
        int f = i / 32, q = i % 32;
        g_w1p[i] = fpack(w1[(2 * q) * F_ + f] * s1[2 * q],
                         w1[(2 * q + 1) * F_ + f] * s1[2 * q + 1]);
    }
    for (int i = t; i < 32 * 64; i += blockDim.x) {
        int q = i / 64, c = i % 64;
        g_w2p[i] = fpack(w2[(2 * q) * C_ + c] * s2[2 * q],
                         w2[(2 * q + 1) * C_ + c] * s2[2 * q + 1]);
    }
    if (t < 32) {
        g_b1p[t] = fpack(bb1[2 * t], bb1[2 * t + 1]);
        g_b2p[t] = fpack(bb2[2 * t], bb2[2 * t + 1]);
    }
}

// ---------------- window occupancy ----------------
__global__ void k_zero_cnt() {
    int i = blockIdx.x * blockDim.x + threadIdx.x;
    if (i < NWIN) g_cnt[i] = 0;
}
__global__ void k_count(const int* __restrict__ coords) {
    int g = blockIdx.x * blockDim.x + threadIdx.x;
    if (g < NPTS) {
        int b = coords[g * 4 + 0];
        int y = coords[g * 4 + 2];
        int x = coords[g * 4 + 3];
        atomicAdd(&g_cnt[(b * NY_ + y) * NXO_ + x / 100], 1);
    }
}
// init out: z[c] for windows with an empty cell (always in practice), else 0
__global__ void k_init(float* __restrict__ out) {
    int i = blockIdx.x * blockDim.x + threadIdx.x;
    if (i < NOUT) {
        int xo = i & 3;
        int y  = (i >> 2) % NY_;
        int c  = (i / (NY_ * NXO_)) & (C_ - 1);
        int b  = i / (C_ * NY_ * NXO_);
        out[i] = (g_cnt[(b * NY_ + y) * NXO_ + xo] < 100) ? g_z[c] : 0.0f;
    }
}

// ---------------- main fused kernel ----------------
// Block: 256 threads = 8 warps. lane = point (32 points/block), warp owns 4
// channel-pairs (8 channels). Stage-1 weights live in registers; x is staged
// through shared with register double-buffering. Stage 2 (64x64 GEMV) fused
// via a shared feat exchange, then scattered with atomicMax into pooled out.
__global__ __launch_bounds__(TPB) void k_main(const float* __restrict__ x,
                                              const int* __restrict__ coords,
                                              float* __restrict__ out) {
    __shared__ float xs[XSN];
    __shared__ ull   w2s[32 * 64];
    __shared__ float feat[NPB][65];

    const int tid  = threadIdx.x;
    const int warp = tid >> 5;
    const int lane = tid & 31;
    const int g0   = blockIdx.x * NPB;      // first point id of block
    const int b    = g0 / P_;               // block never crosses batch (12000 % 32 == 0)
    const int pb   = g0 % P_;

    // w2' pairs to shared (used in stage 2)
    #pragma unroll
    for (int i = tid; i < 32 * 64; i += TPB) w2s[i] = g_w2p[i];

    // stage-1 weights into registers (uniform within warp)
    ull w1r[4][F_];
    #pragma unroll
    for (int j = 0; j < 4; j++)
        #pragma unroll
        for (int f = 0; f < F_; f++)
            w1r[j][f] = g_w1p[f * 32 + warp * 4 + j];

    ull b1r[4];
    #pragma unroll
    for (int j = 0; j < 4; j++) b1r[j] = g_b1p[warp * 4 + j];

    const float* xb = x + (size_t)b * F_ * MP_ * P_ + pb;

    // register staging: prefetch chunk 0
    float st[12];
    #pragma unroll
    for (int k = 0; k < 12; k++) {
        int idx = tid + k * TPB;
        if (idx < XSN) {
            int f   = idx / (MPT * NPB);
            int r   = idx - f * (MPT * NPB);
            int mpi = r >> 5;
            int ln  = r & 31;
            st[k] = xb[(size_t)f * (MP_ * P_) + (size_t)mpi * P_ + ln];
        }
    }

    ull m[4];
    #pragma unroll
    for (int j = 0; j < 4; j++) m[j] = 0ull;  // (+0,+0): implements the ReLU floor

    for (int ch = 0; ch < NCH; ++ch) {
        __syncthreads();
        #pragma unroll
        for (int k = 0; k < 12; k++) {
            int idx = tid + k * TPB;
            if (idx < XSN) xs[idx] = st[k];
        }
        __syncthreads();
        if (ch + 1 < NCH) {  // prefetch next chunk; LDG latency hidden under compute
            #pragma unroll
            for (int k = 0; k < 12; k++) {
                int idx = tid + k * TPB;
                if (idx < XSN) {
                    int f   = idx / (MPT * NPB);
                    int r   = idx - f * (MPT * NPB);
                    int mpi = r >> 5;
                    int ln  = r & 31;
                    st[k] = xb[(size_t)f * (MP_ * P_) + (size_t)((ch + 1) * MPT + mpi) * P_ + ln];
                }
            }
        }
        #pragma unroll
        for (int mpi = 0; mpi < MPT; ++mpi) {
            ull xd[F_];
            #pragma unroll
            for (int f = 0; f < F_; f++)
                xd[f] = fdup(xs[(f * MPT + mpi) * NPB + lane]);
            ull a0 = b1r[0], a1 = b1r[1], a2 = b1r[2], a3 = b1r[3];
            #pragma unroll
            for (int f = 0; f < F_; f++) {
                a0 = ffma2(xd[f], w1r[0][f], a0);
                a1 = ffma2(xd[f], w1r[1][f], a1);
                a2 = ffma2(xd[f], w1r[2][f], a2);
                a3 = ffma2(xd[f], w1r[3][f], a3);
            }
            m[0] = fmax2(m[0], a0);
            m[1] = fmax2(m[1], a1);
            m[2] = fmax2(m[2], a2);
            m[3] = fmax2(m[3], a3);
        }
    }

    // exchange feat (point-major, padded 65 -> bank-conflict-free)
    #pragma unroll
    for (int j = 0; j < 4; j++) {
        float lo, hi;
        funpack(m[j], lo, hi);
        int c0 = (warp * 4 + j) * 2;
        feat[lane][c0]     = lo;
        feat[lane][c0 + 1] = hi;
    }
    __syncthreads();

    // stage 2: 64->64 affine for this lane's point, this warp's 8 channels
    ull acc[4];
    #pragma unroll
    for (int j = 0; j < 4; j++) acc[j] = g_b2p[warp * 4 + j];
    #pragma unroll 8
    for (int c = 0; c < C_; c++) {
        ull fd = fdup(feat[lane][c]);
        #pragma unroll
        for (int j = 0; j < 4; j++)
            acc[j] = ffma2(fd, w2s[(warp * 4 + j) * 64 + c], acc[j]);
    }

    // scatter-max into pooled output; signed-int max == float max for the
    // >=0 init, and negative bit patterns lose to >=0 => free ReLU.
    const int g  = g0 + lane;
    const int bb = coords[g * 4 + 0];
    const int yy = coords[g * 4 + 2];
    const int xx = coords[g * 4 + 3];
    const int xo = xx / 100;
    int* oi = (int*)out;
    #pragma unroll
    for (int j = 0; j < 4; j++) {
        float lo, hi;
        funpack(acc[j], lo, hi);
        int c0 = (warp * 4 + j) * 2;
        atomicMax(&oi[((bb * C_ + c0) * NY_ + yy) * NXO_ + xo], __float_as_int(lo));
        atomicMax(&oi[((bb * C_ + c0 + 1) * NY_ + yy) * NXO_ + xo], __float_as_int(hi));
    }
}

// ---------------- launch ----------------
extern "C" void kernel_launch(void* const* d_in, const int* in_sizes, int n_in,
                              void* d_out, int out_size) {
    const float* x      = (const float*)d_in[0];
    const int*   coords = (const int*)d_in[1];
    const float* w1  = (const float*)d_in[2];
    const float* b1  = (const float*)d_in[3];
    const float* g1  = (const float*)d_in[4];
    const float* be1 = (const float*)d_in[5];
    const float* m1  = (const float*)d_in[6];
    const float* v1  = (const float*)d_in[7];
    const float* w2  = (const float*)d_in[8];
    const float* b2  = (const float*)d_in[9];
    const float* g2  = (const float*)d_in[10];
    const float* be2 = (const float*)d_in[11];
    const float* m2  = (const float*)d_in[12];
    const float* v2  = (const float*)d_in[13];
    float* out = (float*)d_out;

    k_prep<<<1, 256>>>(w1, b1, g1, be1, m1, v1, w2, b2, g2, be2, m2, v2);
    k_zero_cnt<<<(NWIN + 255) / 256, 256>>>();
    k_count<<<(NPTS + 255) / 256, 256>>>(coords);
    k_init<<<(NOUT + 255) / 256, 256>>>(out);
    k_main<<<NPTS / NPB, TPB>>>(x, coords, out);
}

// round 2
// speedup vs baseline: 1.2999x; 1.2999x over previous
#include <cuda_runtime.h>
#include <cstdint>

typedef unsigned long long ull;

// ---------------- problem constants ----------------
#define B_   4
#define F_   9
#define MP_  100
#define P_   12000
#define C_   64
#define NY_  400
#define NX_  400
#define NXO_ 4          // NX / POOL_W
#define NPTS (B_ * P_)  // 48000
#define NWIN (B_ * NY_ * NXO_)  // 6400
#define NOUT (B_ * C_ * NY_ * NXO_) // 409600

// main kernel tiling
#define TPB  256
#define NPB  32          // points per block (one per lane)
#define MPT  10          // mp per chunk
#define NCH  (MP_ / MPT) // 10 chunks
#define XSN  (F_ * MPT * NPB) // 2880 floats staged per chunk
#define CPOPS (XSN * 4 / 16)  // 720 cp.async 16B ops per chunk

// ---------------- device scratch (no allocs allowed) ----------------
__device__ ull   g_w1p[F_ * 32];   // packed pairs: [f][q] -> (w1'[2q][f], w1'[2q+1][f])
__device__ ull   g_b1p[32];
__device__ ull   g_w2p[32 * 64];   // [q][c] -> (w2'[2q][c], w2'[2q+1][c])
__device__ ull   g_b2p[32];
__device__ float g_z[C_];
__device__ int   g_cnt[NWIN];

// ---------------- f32x2 helpers (Blackwell packed fp32) ----------------
__device__ __forceinline__ ull ffma2(ull a, ull b, ull c) {
    ull d;
    asm("fma.rn.f32x2 %0, %1, %2, %3;" : "=l"(d) : "l"(a), "l"(b), "l"(c));
    return d;
}
__device__ __forceinline__ ull fpack(float x, float y) {
    ull r;
    asm("mov.b64 %0, {%1, %2};" : "=l"(r) : "f"(x), "f"(y));
    return r;
}
__device__ __forceinline__ ull fdup(float x) {
    ull r;
    asm("mov.b64 %0, {%1, %2};" : "=l"(r) : "f"(x), "f"(x));
    return r;
}
__device__ __forceinline__ void funpack(ull v, float& x, float& y) {
    asm("mov.b64 {%0, %1}, %2;" : "=f"(x), "=f"(y) : "l"(v));
}
__device__ __forceinline__ ull fmax2(ull a, ull b) {
    float ax, ay, bx, by;
    funpack(a, ax, ay);
    funpack(b, bx, by);
    return fpack(fmaxf(ax, bx), fmaxf(ay, by));
}
__device__ __forceinline__ uint32_t smem_u32(const void* p) {
    return (uint32_t)__cvta_generic_to_shared(p);
}
__device__ __forceinline__ void cp16(uint32_t dst, const float* src) {
    asm volatile("cp.async.ca.shared.global [%0], [%1], 16;" :: "r"(dst), "l"(src));
}

// ---------------- setup: BN fold + pack + window occupancy count ----------
// Single block. Merging prep/zero/count keeps the per-iteration launch count
// at 3 so ncu (-s 5 -c 1) captures k_main.
__global__ void k_setup(const int* __restrict__ coords,
                        const float* __restrict__ w1, const float* __restrict__ b1,
                        const float* __restrict__ g1, const float* __restrict__ be1,
                        const float* __restrict__ m1, const float* __restrict__ v1,
                        const float* __restrict__ w2, const float* __restrict__ b2,
                        const float* __restrict__ g2, const float* __restrict__ be2,
                        const float* __restrict__ m2, const float* __restrict__ v2) {
    __shared__ float s1[C_], bb1[C_], s2[C_], bb2[C_];
    int t = threadIdx.x;
    if (t < C_) {
        float s = g1[t] * rsqrtf(v1[t] + 1e-3f);
        s1[t] = s;
        bb1[t] = b1[t] * s + be1[t] - m1[t] * s;
        float ss = g2[t] * rsqrtf(v2[t] + 1e-3f);
        s2[t] = ss;
        float bz = b2[t] * ss + be2[t] - m2[t] * ss;
        bb2[t] = bz;
        g_z[t] = fmaxf(bz, 0.0f);
    }
    for (int i = t; i < NWIN; i += 256) g_cnt[i] = 0;
    __syncthreads();
    for (int i = t; i < F_ * 32; i += 256) {
        int f = i / 32, q = i % 32;
        g_w1p[i] = fpack(w1[(2 * q) * F_ + f] * s1[2 * q],
                         w1[(2 * q + 1) * F_ + f] * s1[2 * q + 1]);
    }
    for (int i = t; i < 32 * 64; i += 256) {
        int q = i / 64, c = i % 64;
        g_w2p[i] = fpack(w2[(2 * q) * C_ + c] * s2[2 * q],
                         w2[(2 * q + 1) * C_ + c] * s2[2 * q + 1]);
    }
    if (t < 32) {
        g_b1p[t] = fpack(bb1[2 * t], bb1[2 * t + 1]);
        g_b2p[t] = fpack(bb2[2 * t], bb2[2 * t + 1]);
    }
    for (int g = t; g < NPTS; g += 256) {
        int b = coords[g * 4 + 0];
        int y = coords[g * 4 + 2];
        int x = coords[g * 4 + 3];
        atomicAdd(&g_cnt[(b * NY_ + y) * NXO_ + x / 100], 1);
    }
}

// init out: z[c] for windows with an empty cell, else 0 (atomicMax floor)
__global__ void k_init(float* __restrict__ out) {
    int i = blockIdx.x * blockDim.x + threadIdx.x;
    if (i < NOUT) {
        int xo = i & 3;
        int y  = (i >> 2) % NY_;
        int c  = (i / (NY_ * NXO_)) & (C_ - 1);
        int b  = i / (C_ * NY_ * NXO_);
        out[i] = (g_cnt[(b * NY_ + y) * NXO_ + xo] < 100) ? g_z[c] : 0.0f;
    }
}

// ---------------- main fused kernel ----------------
// 8 warps; lane = point (32 points/block), warp owns 4 channel-pairs.
// x staged global->shared via cp.async double-buffering (no register staging,
// no STS): lowers register pressure so 2 blocks/SM fit without spills.
__global__ void __launch_bounds__(TPB, 2) k_main(const float* __restrict__ x,
                                                 const int* __restrict__ coords,
                                                 float* __restrict__ out) {
    __shared__ float xs[2][XSN];
    __shared__ ull   w2s[32 * 64];
    __shared__ float feat[NPB][65];

    const int tid  = threadIdx.x;
    const int warp = tid >> 5;
    const int lane = tid & 31;
    const int g0   = blockIdx.x * NPB;      // first point id of block
    const int b    = g0 / P_;               // block never crosses batch (12000 % 32 == 0)
    const int pb   = g0 % P_;

    // w2' pairs to shared (used in stage 2)
    for (int i = tid; i < 32 * 64; i += TPB) w2s[i] = g_w2p[i];

    // stage-1 weights into registers (uniform within warp)
    ull w1r[4][F_];
    #pragma unroll
    for (int j = 0; j < 4; j++)
        #pragma unroll
        for (int f = 0; f < F_; f++)
            w1r[j][f] = g_w1p[f * 32 + warp * 4 + j];

    ull b1r[4];
    #pragma unroll
    for (int j = 0; j < 4; j++) b1r[j] = g_b1p[warp * 4 + j];

    const float* xb = x + (size_t)b * F_ * MP_ * P_ + pb;

    // cp.async indexing (fixed per thread): 720 16B ops per chunk, <=3/thread
    // op idx -> f = idx/80, mpi = (idx%80)>>3, quad = idx&7
    int   cp_f[3], cp_mpi[3], cp_q[3];
    bool  cp_on[3];
    #pragma unroll
    for (int k = 0; k < 3; k++) {
        int idx = tid + k * TPB;
        cp_on[k]  = idx < CPOPS;
        int ii    = cp_on[k] ? idx : 0;
        cp_f[k]   = ii / (MPT * 8);
        int r     = ii - cp_f[k] * (MPT * 8);
        cp_mpi[k] = r >> 3;
        cp_q[k]   = r & 7;
    }
    uint32_t xs_base = smem_u32(&xs[0][0]);

    // prefetch chunk 0
    #pragma unroll
    for (int k = 0; k < 3; k++)
        if (cp_on[k])
            cp16(xs_base + ((cp_f[k] * MPT + cp_mpi[k]) * NPB + cp_q[k] * 4) * 4,
                 xb + (size_t)cp_f[k] * (MP_ * P_) + (size_t)cp_mpi[k] * P_ + cp_q[k] * 4);
    asm volatile("cp.async.commit_group;");

    ull m[4];
    #pragma unroll
    for (int j = 0; j < 4; j++) m[j] = 0ull;  // (+0,+0): implements the ReLU floor

    #pragma unroll 1
    for (int ch = 0; ch < NCH; ++ch) {
        const int buf = ch & 1;
        if (ch + 1 < NCH) {
            const int nb = (ch + 1) & 1;
            const int mp0 = (ch + 1) * MPT;
            #pragma unroll
            for (int k = 0; k < 3; k++)
                if (cp_on[k])
                    cp16(xs_base + (nb * XSN + (cp_f[k] * MPT + cp_mpi[k]) * NPB + cp_q[k] * 4) * 4,
                         xb + (size_t)cp_f[k] * (MP_ * P_) + (size_t)(mp0 + cp_mpi[k]) * P_ + cp_q[k] * 4);
            asm volatile("cp.async.commit_group;");
            asm volatile("cp.async.wait_group 1;");
        } else {
            asm volatile("cp.async.wait_group 0;");
        }
        __syncthreads();   // chunk ch visible to all

        const float* xc = &xs[buf][0];
        #pragma unroll
        for (int mpi = 0; mpi < MPT; ++mpi) {
            ull a0 = b1r[0], a1 = b1r[1], a2 = b1r[2], a3 = b1r[3];
            #pragma unroll
            for (int f = 0; f < F_; f++) {
                ull xd = fdup(xc[(f * MPT + mpi) * NPB + lane]);
                a0 = ffma2(xd, w1r[0][f], a0);
                a1 = ffma2(xd, w1r[1][f], a1);
                a2 = ffma2(xd, w1r[2][f], a2);
                a3 = ffma2(xd, w1r[3][f], a3);
            }
            m[0] = fmax2(m[0], a0);
            m[1] = fmax2(m[1], a1);
            m[2] = fmax2(m[2], a2);
            m[3] = fmax2(m[3], a3);
        }
        __syncthreads();   // done reading buf before it is refilled
    }

    // exchange feat (point-major, padded 65 -> bank-conflict-free)
    #pragma unroll
    for (int j = 0; j < 4; j++) {
        float lo, hi;
        funpack(m[j], lo, hi);
        int c0 = (warp * 4 + j) * 2;
        feat[lane][c0]     = lo;
        feat[lane][c0 + 1] = hi;
    }
    __syncthreads();

    // stage 2: 64->64 affine for this lane's point, this warp's 8 channels
    ull acc[4];
    #pragma unroll
    for (int j = 0; j < 4; j++) acc[j] = g_b2p[warp * 4 + j];
    #pragma unroll 8
    for (int c = 0; c < C_; c++) {
        ull fd = fdup(feat[lane][c]);
        #pragma unroll
        for (int j = 0; j < 4; j++)
            acc[j] = ffma2(fd, w2s[(warp * 4 + j) * 64 + c], acc[j]);
    }

    // scatter-max into pooled output; signed-int max == float max for the
    // >=0 init, and negative bit patterns lose to >=0 => free ReLU.
    const int g  = g0 + lane;
    const int bb = coords[g * 4 + 0];
    const int yy = coords[g * 4 + 2];
    const int xx = coords[g * 4 + 3];
    const int xo = xx / 100;
    int* oi = (int*)out;
    #pragma unroll
    for (int j = 0; j < 4; j++) {
        float lo, hi;
        funpack(acc[j], lo, hi);
        int c0 = (warp * 4 + j) * 2;
        atomicMax(&oi[((bb * C_ + c0) * NY_ + yy) * NXO_ + xo], __float_as_int(lo));
        atomicMax(&oi[((bb * C_ + c0 + 1) * NY_ + yy) * NXO_ + xo], __float_as_int(hi));
    }
}

// ---------------- launch ----------------
extern "C" void kernel_launch(void* const* d_in, const int* in_sizes, int n_in,
                              void* d_out, int out_size) {
    const float* x      = (const float*)d_in[0];
    const int*   coords = (const int*)d_in[1];
    const float* w1  = (const float*)d_in[2];
    const float* b1  = (const float*)d_in[3];
    const float* g1  = (const float*)d_in[4];
    const float* be1 = (const float*)d_in[5];
    const float* m1  = (const float*)d_in[6];
    const float* v1  = (const float*)d_in[7];
    const float* w2  = (const float*)d_in[8];
    const float* b2  = (const float*)d_in[9];
    const float* g2  = (const float*)d_in[10];
    const float* be2 = (const float*)d_in[11];
    const float* m2  = (const float*)d_in[12];
    const float* v2  = (const float*)d_in[13];
    float* out = (float*)d_out;

    k_setup<<<1, 256>>>(coords, w1, b1, g1, be1, m1, v1, w2, b2, g2, be2, m2, v2);
    k_init<<<(NOUT + 255) / 256, 256>>>(out);
    k_main<<<NPTS / NPB, TPB>>>(x, coords, out);
}

// round 3
// speedup vs baseline: 1.5692x; 1.2072x over previous
#include <cuda_runtime.h>
#include <cstdint>

typedef unsigned long long ull;

// ---------------- problem constants ----------------
#define B_   4
#define F_   9
#define MP_  100
#define P_   12000
#define C_   64
#define NY_  400
#define NX_  400
#define NXO_ 4          // NX / POOL_W
#define NPTS (B_ * P_)  // 48000
#define NWIN (B_ * NY_ * NXO_)  // 6400
#define NOUT (B_ * C_ * NY_ * NXO_) // 409600

// main kernel tiling
#define TPB  256
#define NPB  32          // points per block (one per lane)
#define MPT  10          // mp per chunk
#define NCH  (MP_ / MPT) // 10 chunks
#define XSN  (F_ * MPT * NPB) // 2880 floats staged per chunk
#define CPOPS (XSN * 4 / 16)  // 720 cp.async 16B ops per chunk

// ---------------- device scratch (no allocs allowed) ----------------
__device__ ull   g_w1p[F_ * 32];   // packed pairs: [f][q] -> (w1'[2q][f], w1'[2q+1][f])
__device__ ull   g_b1p[32];
__device__ ull   g_w2p[32 * 64];   // [q][c] -> (w2'[2q][c], w2'[2q+1][c])
__device__ ull   g_b2p[32];
__device__ float g_z[C_];
__device__ int   g_cnt[NWIN];

// ---------------- f32x2 helpers (Blackwell packed fp32) ----------------
__device__ __forceinline__ ull ffma2(ull a, ull b, ull c) {
    ull d;
    asm("fma.rn.f32x2 %0, %1, %2, %3;" : "=l"(d) : "l"(a), "l"(b), "l"(c));
    return d;
}
__device__ __forceinline__ ull fpack(float x, float y) {
    ull r;
    asm("mov.b64 %0, {%1, %2};" : "=l"(r) : "f"(x), "f"(y));
    return r;
}
__device__ __forceinline__ ull fdup(float x) {
    ull r;
    asm("mov.b64 %0, {%1, %2};" : "=l"(r) : "f"(x), "f"(x));
    return r;
}
__device__ __forceinline__ void funpack(ull v, float& x, float& y) {
    asm("mov.b64 {%0, %1}, %2;" : "=f"(x), "=f"(y) : "l"(v));
}
__device__ __forceinline__ ull fmax2(ull a, ull b) {
    float ax, ay, bx, by;
    funpack(a, ax, ay);
    funpack(b, bx, by);
    return fpack(fmaxf(ax, bx), fmaxf(ay, by));
}
__device__ __forceinline__ uint32_t smem_u32(const void* p) {
    return (uint32_t)__cvta_generic_to_shared(p);
}
__device__ __forceinline__ void cp16(uint32_t dst, const float* src) {
    asm volatile("cp.async.ca.shared.global [%0], [%1], 16;" :: "r"(dst), "l"(src));
}

// ---------------- setup: BN fold + weight packing + zero counters --------
// Single small block; the heavy 48k-point counting moved to k_count.
__global__ void k_setup(const float* __restrict__ w1, const float* __restrict__ b1,
                        const float* __restrict__ g1, const float* __restrict__ be1,
                        const float* __restrict__ m1, const float* __restrict__ v1,
                        const float* __restrict__ w2, const float* __restrict__ b2,
                        const float* __restrict__ g2, const float* __restrict__ be2,
                        const float* __restrict__ m2, const float* __restrict__ v2) {
    __shared__ float s1[C_], bb1[C_], s2[C_], bb2[C_];
    int t = threadIdx.x;
    if (t < C_) {
        float s = g1[t] * rsqrtf(v1[t] + 1e-3f);
        s1[t] = s;
        bb1[t] = b1[t] * s + be1[t] - m1[t] * s;
        float ss = g2[t] * rsqrtf(v2[t] + 1e-3f);
        s2[t] = ss;
        float bz = b2[t] * ss + be2[t] - m2[t] * ss;
        bb2[t] = bz;
        g_z[t] = fmaxf(bz, 0.0f);
    }
    for (int i = t; i < NWIN; i += 1024) g_cnt[i] = 0;
    __syncthreads();
    for (int i = t; i < F_ * 32; i += 1024) {
        int f = i / 32, q = i % 32;
        g_w1p[i] = fpack(w1[(2 * q) * F_ + f] * s1[2 * q],
                         w1[(2 * q + 1) * F_ + f] * s1[2 * q + 1]);
    }
    for (int i = t; i < 32 * 64; i += 1024) {
        int q = i / 64, c = i % 64;
        g_w2p[i] = fpack(w2[(2 * q) * C_ + c] * s2[2 * q],
                         w2[(2 * q + 1) * C_ + c] * s2[2 * q + 1]);
    }
    if (t < 32) {
        g_b1p[t] = fpack(bb1[2 * t], bb1[2 * t + 1]);
        g_b2p[t] = fpack(bb2[2 * t], bb2[2 * t + 1]);
    }
}

// grid-wide window occupancy count: one int4 coord load + one RED per thread
__global__ void k_count(const int* __restrict__ coords) {
    int g = blockIdx.x * blockDim.x + threadIdx.x;
    if (g < NPTS) {
        int4 c = ((const int4*)coords)[g];   // x=batch, z=y, w=x
        atomicAdd(&g_cnt[(c.x * NY_ + c.z) * NXO_ + (c.w / 100)], 1);
    }
}

// init out: z[c] for windows with an empty cell, else 0 (atomicMax floor)
__global__ void k_init(float* __restrict__ out) {
    int i = blockIdx.x * blockDim.x + threadIdx.x;
    if (i < NOUT) {
        int xo = i & 3;
        int y  = (i >> 2) % NY_;
        int c  = (i / (NY_ * NXO_)) & (C_ - 1);
        int b  = i / (C_ * NY_ * NXO_);
        out[i] = (g_cnt[(b * NY_ + y) * NXO_ + xo] < 100) ? g_z[c] : 0.0f;
    }
}

// ---------------- main fused kernel ----------------
// 8 warps; lane = point (32 points/block), warp owns 4 channel-pairs.
// x staged global->shared via cp.async double-buffering.
__global__ void __launch_bounds__(TPB, 2) k_main(const float* __restrict__ x,
                                                 const int* __restrict__ coords,
                                                 float* __restrict__ out) {
    __shared__ float xs[2][XSN];
    __shared__ ull   w2s[32 * 64];
    __shared__ float feat[NPB][65];

    const int tid  = threadIdx.x;
    const int warp = tid >> 5;
    const int lane = tid & 31;
    const int g0   = blockIdx.x * NPB;      // first point id of block
    const int b    = g0 / P_;               // block never crosses batch (12000 % 32 == 0)
    const int pb   = g0 % P_;

    // w2' pairs to shared (used in stage 2)
    for (int i = tid; i < 32 * 64; i += TPB) w2s[i] = g_w2p[i];

    // stage-1 weights into registers (uniform within warp)
    ull w1r[4][F_];
    #pragma unroll
    for (int j = 0; j < 4; j++)
        #pragma unroll
        for (int f = 0; f < F_; f++)
            w1r[j][f] = g_w1p[f * 32 + warp * 4 + j];

    ull b1r[4];
    #pragma unroll
    for (int j = 0; j < 4; j++) b1r[j] = g_b1p[warp * 4 + j];

    const float* xb = x + (size_t)b * F_ * MP_ * P_ + pb;

    // cp.async indexing (fixed per thread): 720 16B ops per chunk, <=3/thread
    int   cp_f[3], cp_mpi[3], cp_q[3];
    bool  cp_on[3];
    #pragma unroll
    for (int k = 0; k < 3; k++) {
        int idx = tid + k * TPB;
        cp_on[k]  = idx < CPOPS;
        int ii    = cp_on[k] ? idx : 0;
        cp_f[k]   = ii / (MPT * 8);
        int r     = ii - cp_f[k] * (MPT * 8);
        cp_mpi[k] = r >> 3;
        cp_q[k]   = r & 7;
    }
    uint32_t xs_base = smem_u32(&xs[0][0]);

    // prefetch chunk 0
    #pragma unroll
    for (int k = 0; k < 3; k++)
        if (cp_on[k])
            cp16(xs_base + ((cp_f[k] * MPT + cp_mpi[k]) * NPB + cp_q[k] * 4) * 4,
                 xb + (size_t)cp_f[k] * (MP_ * P_) + (size_t)cp_mpi[k] * P_ + cp_q[k] * 4);
    asm volatile("cp.async.commit_group;");

    ull m[4];
    #pragma unroll
    for (int j = 0; j < 4; j++) m[j] = 0ull;  // (+0,+0): implements the ReLU floor

    #pragma unroll 1
    for (int ch = 0; ch < NCH; ++ch) {
        const int buf = ch & 1;
        if (ch + 1 < NCH) {
            const int nb = (ch + 1) & 1;
            const int mp0 = (ch + 1) * MPT;
            #pragma unroll
            for (int k = 0; k < 3; k++)
                if (cp_on[k])
                    cp16(xs_base + (nb * XSN + (cp_f[k] * MPT + cp_mpi[k]) * NPB + cp_q[k] * 4) * 4,
                         xb + (size_t)cp_f[k] * (MP_ * P_) + (size_t)(mp0 + cp_mpi[k]) * P_ + cp_q[k] * 4);
            asm volatile("cp.async.commit_group;");
            asm volatile("cp.async.wait_group 1;");
        } else {
            asm volatile("cp.async.wait_group 0;");
        }
        __syncthreads();   // chunk ch visible to all

        const float* xc = &xs[buf][0];
        #pragma unroll
        for (int mpi = 0; mpi < MPT; ++mpi) {
            ull a0 = b1r[0], a1 = b1r[1], a2 = b1r[2], a3 = b1r[3];
            #pragma unroll
            for (int f = 0; f < F_; f++) {
                ull xd = fdup(xc[(f * MPT + mpi) * NPB + lane]);
                a0 = ffma2(xd, w1r[0][f], a0);
                a1 = ffma2(xd, w1r[1][f], a1);
                a2 = ffma2(xd, w1r[2][f], a2);
                a3 = ffma2(xd, w1r[3][f], a3);
            }
            m[0] = fmax2(m[0], a0);
            m[1] = fmax2(m[1], a1);
            m[2] = fmax2(m[2], a2);
            m[3] = fmax2(m[3], a3);
        }
        __syncthreads();   // done reading buf before it is refilled
    }

    // exchange feat (point-major, padded 65 -> bank-conflict-free)
    #pragma unroll
    for (int j = 0; j < 4; j++) {
        float lo, hi;
        funpack(m[j], lo, hi);
        int c0 = (warp * 4 + j) * 2;
        feat[lane][c0]     = lo;
        feat[lane][c0 + 1] = hi;
    }
    __syncthreads();

    // stage 2: 64->64 affine for this lane's point, this warp's 8 channels
    ull acc[4];
    #pragma unroll
    for (int j = 0; j < 4; j++) acc[j] = g_b2p[warp * 4 + j];
    #pragma unroll 8
    for (int c = 0; c < C_; c++) {
        ull fd = fdup(feat[lane][c]);
        #pragma unroll
        for (int j = 0; j < 4; j++)
            acc[j] = ffma2(fd, w2s[(warp * 4 + j) * 64 + c], acc[j]);
    }

    // scatter-max into pooled output; signed-int max == float max for the
    // >=0 init, and negative bit patterns lose to >=0 => free ReLU.
    const int g  = g0 + lane;
    const int bb = coords[g * 4 + 0];
    const int yy = coords[g * 4 + 2];
    const int xx = coords[g * 4 + 3];
    const int xo = xx / 100;
    int* oi = (int*)out;
    #pragma unroll
    for (int j = 0; j < 4; j++) {
        float lo, hi;
        funpack(acc[j], lo, hi);
        int c0 = (warp * 4 + j) * 2;
        atomicMax(&oi[((bb * C_ + c0) * NY_ + yy) * NXO_ + xo], __float_as_int(lo));
        atomicMax(&oi[((bb * C_ + c0 + 1) * NY_ + yy) * NXO_ + xo], __float_as_int(hi));
    }
}

// ---------------- launch ----------------
extern "C" void kernel_launch(void* const* d_in, const int* in_sizes, int n_in,
                              void* d_out, int out_size) {
    const float* x      = (const float*)d_in[0];
    const int*   coords = (const int*)d_in[1];
    const float* w1  = (const float*)d_in[2];
    const float* b1  = (const float*)d_in[3];
    const float* g1  = (const float*)d_in[4];
    const float* be1 = (const float*)d_in[5];
    const float* m1  = (const float*)d_in[6];
    const float* v1  = (const float*)d_in[7];
    const float* w2  = (const float*)d_in[8];
    const float* b2  = (const float*)d_in[9];
    const float* g2  = (const float*)d_in[10];
    const float* be2 = (const float*)d_in[11];
    const float* m2  = (const float*)d_in[12];
    const float* v2  = (const float*)d_in[13];
    float* out = (float*)d_out;

    k_setup<<<1, 1024>>>(w1, b1, g1, be1, m1, v1, w2, b2, g2, be2, m2, v2);
    k_count<<<(NPTS + 255) / 256, 256>>>(coords);
    k_init<<<(NOUT + 255) / 256, 256>>>(out);
    k_main<<<NPTS / NPB, TPB>>>(x, coords, out);
}

// round 4
// speedup vs baseline: 1.6011x; 1.0203x over previous
#include <cuda_runtime.h>
#include <cstdint>

typedef unsigned long long ull;

// ---------------- problem constants ----------------
#define B_   4
#define F_   9
#define MP_  100
#define P_   12000
#define C_   64
#define NY_  400
#define NX_  400
#define NXO_ 4          // NX / POOL_W
#define NPTS (B_ * P_)  // 48000
#define NWIN (B_ * NY_ * NXO_)  // 6400
#define NOUT (B_ * C_ * NY_ * NXO_) // 409600

// main kernel tiling
#define TPB  256
#define NPB  32          // points per block (one per lane)
#define MPT  10          // mp per chunk
#define NCH  (MP_ / MPT) // 10 chunks
#define NBUF 3           // pipeline depth
#define XSN  (F_ * MPT * NPB)   // 2880 floats staged per chunk
#define XSNB (XSN * 4)          // bytes per chunk buffer
#define CPOPS (XSN * 4 / 16)    // 720 cp.async 16B ops per chunk
#define CHF   (MPT * P_)        // float stride between chunks in gmem

// ---------------- device scratch (no allocs allowed) ----------------
__device__ ull   g_w1p[F_ * 32];   // packed pairs: [f][q] -> (w1'[2q][f], w1'[2q+1][f])
__device__ ull   g_b1p[32];
__device__ ull   g_w2p[32 * 64];   // [q][c] -> (w2'[2q][c], w2'[2q+1][c])
__device__ ull   g_b2p[32];
__device__ float g_z[C_];
__device__ int   g_cnt[NWIN];

// ---------------- f32x2 helpers (Blackwell packed fp32) ----------------
__device__ __forceinline__ ull ffma2(ull a, ull b, ull c) {
    ull d;
    asm("fma.rn.f32x2 %0, %1, %2, %3;" : "=l"(d) : "l"(a), "l"(b), "l"(c));
    return d;
}
__device__ __forceinline__ ull fpack(float x, float y) {
    ull r;
    asm("mov.b64 %0, {%1, %2};" : "=l"(r) : "f"(x), "f"(y));
    return r;
}
__device__ __forceinline__ ull fdup(float x) {
    ull r;
    asm("mov.b64 %0, {%1, %2};" : "=l"(r) : "f"(x), "f"(x));
    return r;
}
__device__ __forceinline__ void funpack(ull v, float& x, float& y) {
    asm("mov.b64 {%0, %1}, %2;" : "=f"(x), "=f"(y) : "l"(v));
}
__device__ __forceinline__ ull fmax2(ull a, ull b) {
    float ax, ay, bx, by;
    funpack(a, ax, ay);
    funpack(b, bx, by);
    return fpack(fmaxf(ax, bx), fmaxf(ay, by));
}
__device__ __forceinline__ uint32_t smem_u32(const void* p) {
    return (uint32_t)__cvta_generic_to_shared(p);
}
__device__ __forceinline__ void cp16(uint32_t dst, const float* src) {
    asm volatile("cp.async.ca.shared.global [%0], [%1], 16;" :: "r"(dst), "l"(src));
}

// ---------------- setup: BN fold + weight packing + zero counters --------
__global__ void k_setup(const float* __restrict__ w1, const float* __restrict__ b1,
                        const float* __restrict__ g1, const float* __restrict__ be1,
                        const float* __restrict__ m1, const float* __restrict__ v1,
                        const float* __restrict__ w2, const float* __restrict__ b2,
                        const float* __restrict__ g2, const float* __restrict__ be2,
                        const float* __restrict__ m2, const float* __restrict__ v2) {
    __shared__ float s1[C_], bb1[C_], s2[C_], bb2[C_];
    int t = threadIdx.x;
    if (t < C_) {
        float s = g1[t] * rsqrtf(v1[t] + 1e-3f);
        s1[t] = s;
        bb1[t] = b1[t] * s + be1[t] - m1[t] * s;
        float ss = g2[t] * rsqrtf(v2[t] + 1e-3f);
        s2[t] = ss;
        float bz = b2[t] * ss + be2[t] - m2[t] * ss;
        bb2[t] = bz;
        g_z[t] = fmaxf(bz, 0.0f);
    }
    for (int i = t; i < NWIN; i += 1024) g_cnt[i] = 0;
    __syncthreads();
    for (int i = t; i < F_ * 32; i += 1024) {
        int f = i / 32, q = i % 32;
        g_w1p[i] = fpack(w1[(2 * q) * F_ + f] * s1[2 * q],
                         w1[(2 * q + 1) * F_ + f] * s1[2 * q + 1]);
    }
    for (int i = t; i < 32 * 64; i += 1024) {
        int q = i / 64, c = i % 64;
        g_w2p[i] = fpack(w2[(2 * q) * C_ + c] * s2[2 * q],
                         w2[(2 * q + 1) * C_ + c] * s2[2 * q + 1]);
    }
    if (t < 32) {
        g_b1p[t] = fpack(bb1[2 * t], bb1[2 * t + 1]);
        g_b2p[t] = fpack(bb2[2 * t], bb2[2 * t + 1]);
    }
}

// grid-wide window occupancy count: one int4 coord load + one RED per thread
__global__ void k_count(const int* __restrict__ coords) {
    int g = blockIdx.x * blockDim.x + threadIdx.x;
    if (g < NPTS) {
        int4 c = ((const int4*)coords)[g];   // x=batch, z=y, w=x
        atomicAdd(&g_cnt[(c.x * NY_ + c.z) * NXO_ + (c.w / 100)], 1);
    }
}

// init out: z[c] for windows with an empty cell, else 0 (atomicMax floor)
__global__ void k_init(float* __restrict__ out) {
    int i = blockIdx.x * blockDim.x + threadIdx.x;
    if (i < NOUT) {
        int xo = i & 3;
        int y  = (i >> 2) % NY_;
        int c  = (i / (NY_ * NXO_)) & (C_ - 1);
        int b  = i / (C_ * NY_ * NXO_);
        out[i] = (g_cnt[(b * NY_ + y) * NXO_ + xo] < 100) ? g_z[c] : 0.0f;
    }
}

// ---------------- main fused kernel ----------------
// 8 warps; lane = point (32 points/block), warp owns 4 channel-pairs.
// x staged global->shared via 3-deep cp.async pipeline, ONE barrier/chunk.
// Bias-free accumulation (bias + ReLU folded in after the mp-max).
__global__ void __launch_bounds__(TPB, 2) k_main(const float* __restrict__ x,
                                                 const int* __restrict__ coords,
                                                 float* __restrict__ out) {
    __shared__ float xs[NBUF][XSN];
    __shared__ float feat[NPB][65];

    const int tid  = threadIdx.x;
    const int warp = tid >> 5;
    const int lane = tid & 31;
    const int g0   = blockIdx.x * NPB;      // first point id of block
    const int b    = g0 / P_;               // block never crosses batch (12000 % 32 == 0)
    const int pb   = g0 % P_;

    // stage-1 weights into registers (uniform within warp)
    ull w1r[4][F_];
    #pragma unroll
    for (int j = 0; j < 4; j++)
        #pragma unroll
        for (int f = 0; f < F_; f++)
            w1r[j][f] = g_w1p[f * 32 + warp * 4 + j];

    const float* xb = x + (size_t)b * F_ * MP_ * P_ + pb;

    // cp.async assignment (fixed per thread): 720 16B ops/chunk, <=3/thread
    // idx -> f = idx/80, mpi = (idx%80)>>3, quad = idx&7
    const uint32_t xs_base = smem_u32(&xs[0][0]);
    const float* cp_src[3];
    uint32_t     cp_dst[3];
    bool         cp_on[3];
    #pragma unroll
    for (int k = 0; k < 3; k++) {
        int idx = tid + k * TPB;
        cp_on[k] = idx < CPOPS;
        int ii   = cp_on[k] ? idx : 0;
        int f    = ii / (MPT * 8);
        int r    = ii - f * (MPT * 8);
        int mpi  = r >> 3;
        int q    = r & 7;
        cp_src[k] = xb + (size_t)f * (MP_ * P_) + (size_t)mpi * P_ + q * 4;
        cp_dst[k] = xs_base + (uint32_t)(((f * MPT + mpi) * NPB + q * 4) * 4);
    }

    // prologue: prefetch chunks 0 and 1 into bufs 0,1
    #pragma unroll
    for (int k = 0; k < 3; k++)
        if (cp_on[k]) cp16(cp_dst[k], cp_src[k]);
    asm volatile("cp.async.commit_group;");
    #pragma unroll
    for (int k = 0; k < 3; k++)
        if (cp_on[k]) cp16(cp_dst[k] + XSNB, cp_src[k] + CHF);
    asm volatile("cp.async.commit_group;");
    // advance src to chunk-2 position
    #pragma unroll
    for (int k = 0; k < 3; k++) cp_src[k] += 2 * CHF;

    ull m[4];
    #pragma unroll
    for (int j = 0; j < 4; j++) m[j] = 0xFF800000FF800000ull;  // (-inf,-inf)

    int bufc = 0;   // buffer holding chunk ch
    int bufn = 2;   // buffer for chunk ch+2
    #pragma unroll 1
    for (int ch = 0; ch < NCH; ++ch) {
        // wait for this thread's chunk-ch copies (newest group may stay in flight)
        if (ch < NCH - 1) asm volatile("cp.async.wait_group 1;");
        else              asm volatile("cp.async.wait_group 0;");
        __syncthreads();   // chunk ch visible to all; all done reading buf[bufn]

        if (ch + 2 < NCH) {   // prefetch chunk ch+2 into bufn (its data, chunk
                              // ch-1, was fully consumed before the barrier)
            uint32_t d = xs_base + (uint32_t)bufn * XSNB;
            #pragma unroll
            for (int k = 0; k < 3; k++)
                if (cp_on[k]) cp16(d + (cp_dst[k] - xs_base), cp_src[k]);
            asm volatile("cp.async.commit_group;");
            #pragma unroll
            for (int k = 0; k < 3; k++) cp_src[k] += CHF;
        }

        const float* xc = &xs[bufc][0];
        #pragma unroll
        for (int mpi = 0; mpi < MPT; ++mpi) {
            ull xd0 = fdup(xc[(0 * MPT + mpi) * NPB + lane]);
            ull a0 = ffma2(xd0, w1r[0][0], 0ull);
            ull a1 = ffma2(xd0, w1r[1][0], 0ull);
            ull a2 = ffma2(xd0, w1r[2][0], 0ull);
            ull a3 = ffma2(xd0, w1r[3][0], 0ull);
            #pragma unroll
            for (int f = 1; f < F_; f++) {
                ull xd = fdup(xc[(f * MPT + mpi) * NPB + lane]);
                a0 = ffma2(xd, w1r[0][f], a0);
                a1 = ffma2(xd, w1r[1][f], a1);
                a2 = ffma2(xd, w1r[2][f], a2);
                a3 = ffma2(xd, w1r[3][f], a3);
            }
            m[0] = fmax2(m[0], a0);
            m[1] = fmax2(m[1], a1);
            m[2] = fmax2(m[2], a2);
            m[3] = fmax2(m[3], a3);
        }
        bufc = (bufc == NBUF - 1) ? 0 : bufc + 1;
        bufn = (bufn == NBUF - 1) ? 0 : bufn + 1;
    }

    // bias + ReLU after the max (exact: max_mp(Wx+b) = max_mp(Wx)+b),
    // exchange feat (point-major, padded 65 -> bank-conflict-free)
    #pragma unroll
    for (int j = 0; j < 4; j++) {
        float lo, hi, bl, bh;
        funpack(m[j], lo, hi);
        funpack(g_b1p[warp * 4 + j], bl, bh);
        int c0 = (warp * 4 + j) * 2;
        feat[lane][c0]     = fmaxf(lo + bl, 0.0f);
        feat[lane][c0 + 1] = fmaxf(hi + bh, 0.0f);
    }
    __syncthreads();

    // stage 2: 64->64 affine; w2 pairs straight from global (L1/L2 resident,
    // 16KB shared by all blocks)
    const ull* __restrict__ w2g = g_w2p + warp * 4 * 64;
    ull acc[4];
    #pragma unroll
    for (int j = 0; j < 4; j++) acc[j] = g_b2p[warp * 4 + j];
    #pragma unroll 8
    for (int c = 0; c < C_; c++) {
        ull fd = fdup(feat[lane][c]);
        #pragma unroll
        for (int j = 0; j < 4; j++)
            acc[j] = ffma2(fd, w2g[j * 64 + c], acc[j]);
    }

    // scatter-max into pooled output; signed-int max == float max for the
    // >=0 init, and negative bit patterns lose to >=0 => free ReLU.
    const int g  = g0 + lane;
    const int bb = coords[g * 4 + 0];
    const int yy = coords[g * 4 + 2];
    const int xx = coords[g * 4 + 3];
    const int xo = xx / 100;
    int* oi = (int*)out;
    #pragma unroll
    for (int j = 0; j < 4; j++) {
        float lo, hi;
        funpack(acc[j], lo, hi);
        int c0 = (warp * 4 + j) * 2;
        atomicMax(&oi[((bb * C_ + c0) * NY_ + yy) * NXO_ + xo], __float_as_int(lo));
        atomicMax(&oi[((bb * C_ + c0 + 1) * NY_ + yy) * NXO_ + xo], __float_as_int(hi));
    }
}

// ---------------- launch ----------------
extern "C" void kernel_launch(void* const* d_in, const int* in_sizes, int n_in,
                              void* d_out, int out_size) {
    const float* x      = (const float*)d_in[0];
    const int*   coords = (const int*)d_in[1];
    const float* w1  = (const float*)d_in[2];
    const float* b1  = (const float*)d_in[3];
    const float* g1  = (const float*)d_in[4];
    const float* be1 = (const float*)d_in[5];
    const float* m1  = (const float*)d_in[6];
    const float* v1  = (const float*)d_in[7];
    const float* w2  = (const float*)d_in[8];
    const float* b2  = (const float*)d_in[9];
    const float* g2  = (const float*)d_in[10];
    const float* be2 = (const float*)d_in[11];
    const float* m2  = (const float*)d_in[12];
    const float* v2  = (const float*)d_in[13];
    float* out = (float*)d_out;

    k_setup<<<1, 1024>>>(w1, b1, g1, be1, m1, v1, w2, b2, g2, be2, m2, v2);
    k_count<<<(NPTS + 255) / 256, 256>>>(coords);
    k_init<<<(NOUT + 255) / 256, 256>>>(out);
    k_main<<<NPTS / NPB, TPB>>>(x, coords, out);
}